// round 14
// baseline (speedup 1.0000x reference)
#include <cuda_runtime.h>
#include <math.h>

#define BB    16
#define CIN   64
#define COUT  64
#define NN    16384
#define NF    8192      // complex FFT size (N/2)
#define MODES 2048
#define TEMB  512

// Skewed shared index: every 8 complexes insert 1 pad -> tames smem bank
// conflicts of the strided Stockham stores.
#define IDX(a) ((a) + ((a) >> 3))
#define SBUF   9216      // IDX(8191)=9214 < 9216  -> 73728 bytes (single buffer)

// ---------------- scratch (static device memory; no allocation) -------------
__device__ float2 g_Xm[BB * CIN * MODES];   // forward modes (+temb bias)
__device__ float2 g_Om[BB * COUT * MODES];  // contracted modes

#define ASTEP (-7.66990393942820615e-4f)    // -2*pi/8192
#define BSTEP (-3.83495196971410307e-4f)    // -2*pi/16384

// ---------------- complex helpers -------------------------------------------
__device__ __forceinline__ float2 cmulf(float2 a, float2 b) {
    return make_float2(fmaf(a.x, b.x, -a.y * b.y), fmaf(a.x, b.y, a.y * b.x));
}
__device__ __forceinline__ float2 caddf(float2 a, float2 b) {
    return make_float2(a.x + b.x, a.y + b.y);
}
__device__ __forceinline__ float2 csubf(float2 a, float2 b) {
    return make_float2(a.x - b.x, a.y - b.y);
}
__device__ __forceinline__ float2 twid(float ang) {
    float s, c;
    __sincosf(ang, &s, &c);
    return make_float2(c, s);
}

// packed fp32x2 fma (FFMA2) — used in the einsum only
__device__ __forceinline__ unsigned long long fma2(unsigned long long a,
                                                   unsigned long long b,
                                                   unsigned long long c) {
    unsigned long long d;
    asm("fma.rn.f32x2 %0, %1, %2, %3;" : "=l"(d) : "l"(a), "l"(b), "l"(c));
    return d;
}

// DFT4 (forward, e^{-2pi i rk/4}), natural-order out
__device__ __forceinline__ void dft4(float2 a, float2 b, float2 c, float2 d, float2 y[4]) {
    float2 t0 = caddf(a, c), t1 = csubf(a, c);
    float2 t2 = caddf(b, d), t3 = csubf(b, d);
    y[0] = caddf(t0, t2);
    y[2] = csubf(t0, t2);
    y[1] = make_float2(t1.x + t3.y, t1.y - t3.x);   // t1 - i*t3
    y[3] = make_float2(t1.x - t3.y, t1.y + t3.x);   // t1 + i*t3
}

// DFT8 (forward), natural-order in/out
__device__ __forceinline__ void fft8(float2 v[8]) {
    const float c = 0.70710678118654752f;
    float2 e[4], o[4];
    dft4(v[0], v[2], v[4], v[6], e);
    dft4(v[1], v[3], v[5], v[7], o);
    float2 o0 = o[0];
    float2 o1 = make_float2(c * (o[1].x + o[1].y), c * (o[1].y - o[1].x)); // *(c,-c)
    float2 o2 = make_float2(o[2].y, -o[2].x);                             // *(-i)
    float2 o3 = make_float2(c * (o[3].y - o[3].x), -c * (o[3].x + o[3].y)); // *(-c,-c)
    v[0] = caddf(e[0], o0);  v[4] = csubf(e[0], o0);
    v[1] = caddf(e[1], o1);  v[5] = csubf(e[1], o1);
    v[2] = caddf(e[2], o2);  v[6] = csubf(e[2], o2);
    v[3] = caddf(e[3], o3);  v[7] = csubf(e[3], o3);
}

// ---- shared stage-1 of DFT16 (4 dft4s + constant twiddles) -----------------
__device__ __forceinline__ void fft16_stage1(const float2 v[16],
                                             float2 y0[4], float2 y1[4],
                                             float2 y2[4], float2 y3[4]) {
    const float c1 = 0.92387953251128675f;   // cos(pi/8)
    const float s1 = 0.38268343236508977f;   // sin(pi/8)
    const float c2 = 0.70710678118654752f;
    dft4(v[0], v[4], v[8],  v[12], y0);
    dft4(v[1], v[5], v[9],  v[13], y1);
    dft4(v[2], v[6], v[10], v[14], y2);
    dft4(v[3], v[7], v[11], v[15], y3);
    y1[1] = cmulf(y1[1], make_float2( c1, -s1));
    y1[2] = cmulf(y1[2], make_float2( c2, -c2));
    y1[3] = cmulf(y1[3], make_float2( s1, -c1));
    y2[1] = cmulf(y2[1], make_float2( c2, -c2));
    y2[2] = make_float2(y2[2].y, -y2[2].x);                 // * (-i)
    y2[3] = cmulf(y2[3], make_float2(-c2, -c2));
    y3[1] = cmulf(y3[1], make_float2( s1, -c1));
    y3[2] = cmulf(y3[2], make_float2(-c2, -c2));
    y3[3] = cmulf(y3[3], make_float2(-c1,  s1));            // W16^9
}

// DFT16 (forward), natural-order in/out; full 16 outputs (inverse path).
__device__ __forceinline__ void fft16(float2 v[16]) {
    float2 y0[4], y1[4], y2[4], y3[4];
    fft16_stage1(v, y0, y1, y2, y3);
    float2 z[4];
    dft4(y0[0], y1[0], y2[0], y3[0], z); v[0]=z[0]; v[4]=z[1]; v[8] =z[2]; v[12]=z[3];
    dft4(y0[1], y1[1], y2[1], y3[1], z); v[1]=z[0]; v[5]=z[1]; v[9] =z[2]; v[13]=z[3];
    dft4(y0[2], y1[2], y2[2], y3[2], z); v[2]=z[0]; v[6]=z[1]; v[10]=z[2]; v[14]=z[3];
    dft4(y0[3], y1[3], y2[3], y3[3], z); v[3]=z[0]; v[7]=z[1]; v[11]=z[2]; v[15]=z[3];
}

// DFT16 pruned for the forward path: only outputs r in {0..3, 12..15}.
// Final dft4 bank emits z0 = t0+t2 and z3 = t1+i*t3 only (6 adds vs 8).
__device__ __forceinline__ void fft16_fwd(float2 v[16]) {
    float2 y0[4], y1[4], y2[4], y3[4];
    fft16_stage1(v, y0, y1, y2, y3);
#pragma unroll
    for (int k = 0; k < 4; k++) {
        float2 t0 = caddf(y0[k], y2[k]), t1 = csubf(y0[k], y2[k]);
        float2 t2 = caddf(y1[k], y3[k]), t3 = csubf(y1[k], y3[k]);
        v[k]      = caddf(t0, t2);
        v[k + 12] = make_float2(t1.x - t3.y, t1.y + t3.x);   // t1 + i*t3
    }
}

// ---- stage-1/2 twiddle tables in shared (8 + 64 distinct sets of 7) --------
// Precompute with <=1 direct sincos per thread; published by the stage-0
// __syncthreads that precedes fft_stages12.
#define TW1_N 56     // 8 t-values * 7 powers
#define TW2_N 448    // 64 t-values * 7 powers
__device__ __forceinline__ void tw_precompute(float2* tw1, float2* tw2, int tid) {
    if (tid < TW1_N) {                       // stage 1: Ns=8, shift=7
        const int tt = tid / 7, k = tid % 7 + 1;
        tw1[tid] = twid((float)((k * tt) << 7) * ASTEP);
    }
    if (tid >= 64 && tid < 64 + TW2_N) {     // stage 2: Ns=64, shift=4
        const int idx = tid - 64;
        const int tt = idx / 7, k = idx % 7 + 1;
        tw2[idx] = twid((float)((k * tt) << 4) * ASTEP);
    }
}

// ---- middle radix-8 stages (s = 1, 2) of the 8192-pt Stockham FFT ----------
// Twiddles from shared tables (per-t shared across the 2 half-butterflies).
__device__ void fft_stages12(float2* S, const float2* tw1, const float2* tw2) {
    const int tid = threadIdx.x;
#pragma unroll
    for (int s = 1; s < 3; s++) {
        const int Ns = 1 << (3 * s);
        const int t = tid & (Ns - 1);
        const float2* twp = (s == 1) ? (tw1 + t * 7) : (tw2 + t * 7);
        const float2 w1 = twp[0];
        const float2 w2 = twp[1];
        const float2 w3 = twp[2];
        const float2 w4 = twp[3];
        const float2 w5 = twp[4];
        const float2 w6 = twp[5];
        const float2 w7 = twp[6];
        float2 v[2][8];
        int base[2];
#pragma unroll
        for (int h = 0; h < 2; h++) {
            const int j = tid + (h << 9);
#pragma unroll
            for (int r = 0; r < 8; r++) v[h][r] = S[IDX(j + (r << 10))];
            v[h][1] = cmulf(v[h][1], w1);
            v[h][2] = cmulf(v[h][2], w2);
            v[h][3] = cmulf(v[h][3], w3);
            v[h][4] = cmulf(v[h][4], w4);
            v[h][5] = cmulf(v[h][5], w5);
            v[h][6] = cmulf(v[h][6], w6);
            v[h][7] = cmulf(v[h][7], w7);
            fft8(v[h]);
            base[h] = ((j >> (3 * s)) << (3 * s + 3)) + t;  // (j/Ns)*8Ns + t
        }
        __syncthreads();
#pragma unroll
        for (int h = 0; h < 2; h++)
#pragma unroll
            for (int r = 0; r < 8; r++)
                S[IDX(base[h] + (r << (3 * s)))] = v[h][r];
        __syncthreads();
    }
}

// ---- final radix-16 load + twiddle (shared by fwd/inv) ---------------------
__device__ __forceinline__ void radix16_load(const float2* S, int j, float2 v[16]) {
#pragma unroll
    for (int r = 0; r < 16; r++) v[r] = S[IDX(j + (r << 9))];
    const float2 w1 = twid((float)j * ASTEP);
    const float2 w2 = cmulf(w1, w1);
    const float2 w3 = cmulf(w2, w1);
    const float2 w4 = cmulf(w2, w2);
    const float2 w5 = cmulf(w4, w1);
    const float2 w6 = cmulf(w4, w2);
    const float2 w7 = cmulf(w4, w3);
    const float2 w8 = cmulf(w4, w4);
    v[1]  = cmulf(v[1],  w1);
    v[2]  = cmulf(v[2],  w2);
    v[3]  = cmulf(v[3],  w3);
    v[4]  = cmulf(v[4],  w4);
    v[5]  = cmulf(v[5],  w5);
    v[6]  = cmulf(v[6],  w6);
    v[7]  = cmulf(v[7],  w7);
    v[8]  = cmulf(v[8],  w8);
    v[9]  = cmulf(v[9],  cmulf(w8, w1));
    v[10] = cmulf(v[10], cmulf(w8, w2));
    v[11] = cmulf(v[11], cmulf(w8, w3));
    v[12] = cmulf(v[12], cmulf(w8, w4));
    v[13] = cmulf(v[13], cmulf(w8, w5));
    v[14] = cmulf(v[14], cmulf(w8, w6));
    v[15] = cmulf(v[15], cmulf(w8, w7));
}

// ---------------- kernel: forward rFFT + temb bias (fused) + modes ----------
__global__ void __launch_bounds__(512, 2)
k_fwd(const float* __restrict__ x, const float* __restrict__ temb,
      const float* __restrict__ dw, const float* __restrict__ db) {
    extern __shared__ float2 sm[];
    float2* S = sm;
    __shared__ float2 tw1[TW1_N];
    __shared__ float2 tw2[TW2_N];
    __shared__ float s_part[16];
    __shared__ float s_bias;
    const int row = blockIdx.x;                    // b*64 + c_in
    const int bb  = row >> 6;
    const int cc  = row & 63;
    const float2* xr = (const float2*)x + (size_t)row * NF;
    const int tid = threadIdx.x;

    // ---- bias partial: one product per thread (TEMB == 512 == blockDim) ----
    {
        float tv = __ldg(&temb[bb * TEMB + tid]);
        float act = tv / (1.0f + expf(-tv));       // SiLU
        float prod = act * __ldg(&dw[(size_t)cc * TEMB + tid]);
#pragma unroll
        for (int o = 16; o; o >>= 1) prod += __shfl_xor_sync(0xffffffffu, prod, o);
        if ((tid & 31) == 0) s_part[tid >> 5] = prod;
    }
    tw_precompute(tw1, tw2, tid);                  // overlaps stage-0 loads

    // stage 0: Ns=1, twiddle-free, inputs straight from gmem (streaming)
    {
        float2 v[2][8];
#pragma unroll
        for (int h = 0; h < 2; h++) {
            const int j = tid + (h << 9);
#pragma unroll
            for (int r = 0; r < 8; r++) v[h][r] = __ldcs(&xr[j + (r << 10)]);
            fft8(v[h]);
        }
#pragma unroll
        for (int h = 0; h < 2; h++) {
            const int base = (tid + (h << 9)) << 3;
#pragma unroll
            for (int r = 0; r < 8; r++) S[IDX(base + r)] = v[h][r];
        }
        __syncthreads();                           // publishes s_part, tw1/2
    }
    if (tid == 0) {                                // finish bias reduction
        float sum = __ldg(&db[cc]);
#pragma unroll
        for (int w = 0; w < 16; w++) sum += s_part[w];
        s_bias = sum;                              // read after later barriers
    }
    fft_stages12(S, tw1, tw2);
    float2 v[16];
    radix16_load(S, tid, v);
    fft16_fwd(v);                                  // only r in {0..3, 12..15}
    __syncthreads();               // stage-2 reads done before overwrite
    // store only the mirror groups r in [12,16): entries 6144..8191
#pragma unroll
    for (int r = 12; r < 16; r++) S[IDX(tid + (r << 9))] = v[r];
    __syncthreads();
    const float tb = s_bias;
    float2* xrow = g_Xm + (size_t)row * MODES;
    // e^{-2pi i m/16384} = e0 * e^{-i pi r/16},  e0 = e^{-2pi i tid/16384}
    const float2 e0 = twid((float)tid * BSTEP);
    const float2 ER[4] = {
        make_float2(1.0f, 0.0f),
        make_float2(0.98078528040323044f, -0.19509032201612827f),
        make_float2(0.92387953251128675f, -0.38268343236508977f),
        make_float2(0.83146961230254524f, -0.55557023301960222f)
    };
#pragma unroll
    for (int r = 0; r < 4; r++) {
        const int m = tid + (r << 9);
        float2 Zm = v[r];
        float2 Zn;
        if (tid == 0) {
            Zn = (r == 0) ? v[0] : v[16 - r];       // Z[8192-512r] is own reg
        } else {
            // 8192-m = (512-tid) + 512*(15-r) -> stored by thread 512-tid
            Zn = S[IDX((512 - tid) + ((15 - r) << 9))];
        }
        float2 A  = make_float2(Zm.x + Zn.x, Zm.y - Zn.y);   // Z + conj(Zn)
        float2 Bc = make_float2(Zm.x - Zn.x, Zm.y + Zn.y);   // Z - conj(Zn)
        float2 C  = cmulf(cmulf(e0, ER[r]), Bc);
        // X = 0.5*A - 0.5*i*C ; add temb bias to real part
        xrow[m] = make_float2(0.5f * (A.x + C.y) + tb, 0.5f * (A.y - C.x));
    }
}

// ---------------- kernel: mode contraction (bim,iom->bom) -------------------
// grid: 256 blocks (8 modes each); block: 256 threads =
//   [bit7]=batch-half x [bits2:7]=32 o-pairs x [bits0:2]=4 mode-pairs.
// Round-8 layout + prefetch.global.L2 at distance 6.
__global__ void __launch_bounds__(256, 2)
k_einsum(const float* __restrict__ wr, const float* __restrict__ wi) {
    extern __shared__ float4 Xc[];                 // [ (b*64+i)*4 + mg ] 64KB
    const int m0  = blockIdx.x * 8;
    const int tid = threadIdx.x;
    for (int idx = tid; idx < BB * CIN * 4; idx += 256) {
        const int p  = idx & 3;
        const int bi = idx >> 2;
        float4 q = *((const float4*)(g_Xm + (size_t)bi * MODES + m0) + p);
        Xc[idx] = make_float4(q.x, q.z, q.y, q.w); // (re0, re1, im0, im1)
    }
    __syncthreads();
    const int mg = tid & 3;
    const int op = (tid >> 2) & 31;
    const int bh = tid >> 7;
    const int o0 = 2 * op;
    const int m  = m0 + 2 * mg;
    const int b0 = bh * 8;

    unsigned long long ar[2][8], ai[2][8];
#pragma unroll
    for (int k = 0; k < 2; k++)
#pragma unroll
        for (int b = 0; b < 8; b++) { ar[k][b] = 0ULL; ai[k][b] = 0ULL; }

    const size_t istep = (size_t)COUT * MODES;
    size_t off = (size_t)o0 * MODES + m;
    unsigned long long cwr0 = *(const unsigned long long*)(wr + off);
    unsigned long long cwr1 = *(const unsigned long long*)(wr + off + MODES);
    unsigned long long cwi0 = *(const unsigned long long*)(wi + off);
    unsigned long long cwi1 = *(const unsigned long long*)(wi + off + MODES);

    for (int i = 0; i < CIN; i++) {
        unsigned long long nwr0, nwr1, nwi0, nwi1;
        if (i + 1 < CIN) {                          // register prefetch, d=1
            const size_t noff = off + istep;
            nwr0 = *(const unsigned long long*)(wr + noff);
            nwr1 = *(const unsigned long long*)(wr + noff + MODES);
            nwi0 = *(const unsigned long long*)(wi + noff);
            nwi1 = *(const unsigned long long*)(wi + noff + MODES);
        }
        if (i + 6 < CIN) {                          // L2 prefetch, distance 6
            const size_t poff = off + 6 * istep;
            asm volatile("prefetch.global.L2 [%0];" :: "l"(wr + poff));
            asm volatile("prefetch.global.L2 [%0];" :: "l"(wr + poff + MODES));
            asm volatile("prefetch.global.L2 [%0];" :: "l"(wi + poff));
            asm volatile("prefetch.global.L2 [%0];" :: "l"(wi + poff + MODES));
        }
#pragma unroll
        for (int b = 0; b < 8; b++) {
            const int idx2 = ((b0 + b) * CIN + i) * 4 + mg;
            const ulonglong2 xu = *(const ulonglong2*)(Xc + idx2); // 1 LDS.128
            const unsigned long long xr2  = xu.x;                  // (re0,re1)
            const unsigned long long xi2  = xu.y;                  // (im0,im1)
            const unsigned long long xin2 = xi2 ^ 0x8000000080000000ULL;
            ar[0][b] = fma2(xr2,  cwr0, ar[0][b]);
            ar[0][b] = fma2(xin2, cwi0, ar[0][b]);
            ai[0][b] = fma2(xr2,  cwi0, ai[0][b]);
            ai[0][b] = fma2(xi2,  cwr0, ai[0][b]);
            ar[1][b] = fma2(xr2,  cwr1, ar[1][b]);
            ar[1][b] = fma2(xin2, cwi1, ar[1][b]);
            ai[1][b] = fma2(xr2,  cwi1, ai[1][b]);
            ai[1][b] = fma2(xi2,  cwr1, ai[1][b]);
        }
        cwr0 = nwr0; cwr1 = nwr1; cwi0 = nwi0; cwi1 = nwi1;
        off += istep;
    }
#pragma unroll
    for (int k = 0; k < 2; k++)
#pragma unroll
        for (int b = 0; b < 8; b++) {
            float r0, r1, i0, i1;
            asm("mov.b64 {%0, %1}, %2;" : "=f"(r0), "=f"(r1) : "l"(ar[k][b]));
            asm("mov.b64 {%0, %1}, %2;" : "=f"(i0), "=f"(i1) : "l"(ai[k][b]));
            const size_t ob = ((size_t)((b0 + b) * COUT + o0 + k)) * MODES + m;
            *((float4*)(g_Om + ob)) = make_float4(r0, i0, r1, i1);
        }
}

// ---------------- kernel: inverse rFFT --------------------------------------
__global__ void __launch_bounds__(512, 2)
k_inv(float* __restrict__ out) {
    extern __shared__ float2 sm[];
    float2* S = sm;
    __shared__ float2 tw1[TW1_N];
    __shared__ float2 tw2[TW2_N];
    const int row = blockIdx.x;                    // b*64 + c_out
    const float2* orow = g_Om + (size_t)row * MODES;
    const int tid = threadIdx.x;
    tw_precompute(tw1, tw2, tid);                  // overlaps stage-0 loads
    // stage 0 (Ns=1, twiddle-free): inputs computed inline
    {
        float2 v[2][8];
#pragma unroll
        for (int h = 0; h < 2; h++) {
            const int j = tid + (h << 9);
            const float2 e0 = twid((float)j * BSTEP);  // e^{-2pi i j/16384}
#pragma unroll
            for (int r = 0; r < 8; r++) {
                if (r >= 2 && r <= 5) { v[h][r] = make_float2(0.0f, 0.0f); continue; }
                const int mm = j + (r << 10);
                float2 Xm = make_float2(0.0f, 0.0f);
                float2 Cc = make_float2(0.0f, 0.0f);
                if (r < 2) {                       // mm < 2048
                    Xm = __ldg(&orow[mm]);
                    if (mm == 0) Xm.y = 0.0f;      // irfft drops Im(X[0])
                } else {                           // r>=6: mirror branch
                    const int mr = NF - mm;
                    if (mr < MODES) {
                        float2 q = __ldg(&orow[mr]);
                        Cc = make_float2(q.x, -q.y);
                    }
                }
                float2 Ze = make_float2(0.5f * (Xm.x + Cc.x), 0.5f * (Xm.y + Cc.y));
                float2 D  = make_float2(0.5f * (Xm.x - Cc.x), 0.5f * (Xm.y - Cc.y));
                // e = e0 * e^{-i pi r/8} (constants for r in {0,1,6,7})
                float2 er;
                if (r == 0)      er = e0;
                else if (r == 1) er = cmulf(e0, make_float2( 0.92387953251128675f, -0.38268343236508977f));
                else if (r == 6) er = cmulf(e0, make_float2(-0.70710678118654752f, -0.70710678118654752f));
                else             er = cmulf(e0, make_float2(-0.92387953251128675f, -0.38268343236508977f));
                float2 Zo = cmulf(make_float2(er.x, -er.y), D);
                // Z = Ze + i*Zo ; store conj(Z) so forward FFT computes inverse
                v[h][r] = make_float2(Ze.x - Zo.y, -(Ze.y + Zo.x));
            }
            fft8(v[h]);
        }
#pragma unroll
        for (int h = 0; h < 2; h++) {
            const int base = (tid + (h << 9)) << 3;
#pragma unroll
            for (int r = 0; r < 8; r++) S[IDX(base + r)] = v[h][r];
        }
        __syncthreads();                           // publishes tw1/tw2
    }
    fft_stages12(S, tw1, tw2);
    // final radix-16: write results straight to gmem (index j + 512r)
    {
        float2 v[16];
        radix16_load(S, tid, v);
        fft16(v);
        const float sc = 1.0f / 8192.0f;
        float2* outr = (float2*)out + (size_t)row * NF;
#pragma unroll
        for (int r = 0; r < 16; r++) {
            float2 z = v[r];
            __stcs(&outr[tid + (r << 9)],
                   make_float2(z.x * sc, -z.y * sc));   // conj + 1/N, streaming
        }
    }
}

// ---------------- launch ----------------------------------------------------
extern "C" void kernel_launch(void* const* d_in, const int* in_sizes, int n_in,
                              void* d_out, int out_size) {
    const float* x    = (const float*)d_in[0];
    const float* temb = (const float*)d_in[1];
    const float* wr   = (const float*)d_in[2];
    const float* wi   = (const float*)d_in[3];
    const float* dw   = (const float*)d_in[4];
    const float* db   = (const float*)d_in[5];
    float* out = (float*)d_out;

    cudaFuncSetAttribute(k_fwd,    cudaFuncAttributeMaxDynamicSharedMemorySize, SBUF * 8);
    cudaFuncSetAttribute(k_inv,    cudaFuncAttributeMaxDynamicSharedMemorySize, SBUF * 8);
    cudaFuncSetAttribute(k_einsum, cudaFuncAttributeMaxDynamicSharedMemorySize, 65536);

    k_fwd   <<<BB * CIN, 512, SBUF * 8>>>(x, temb, dw, db);
    k_einsum<<<MODES / 8, 256, 65536>>>(wr, wi);
    k_inv   <<<BB * COUT, 512, SBUF * 8>>>(out);
}

// round 15
// speedup vs baseline: 1.0207x; 1.0207x over previous
#include <cuda_runtime.h>
#include <math.h>

#define BB    16
#define CIN   64
#define COUT  64
#define NN    16384
#define NF    8192      // complex FFT size (N/2)
#define MODES 2048
#define TEMB  512

// Skewed shared index: every 8 complexes insert 1 pad -> tames smem bank
// conflicts of the strided Stockham stores.
#define IDX(a) ((a) + ((a) >> 3))
#define SBUF   9216      // IDX(8191)=9214 < 9216  -> 73728 bytes (single buffer)

// ---------------- scratch (static device memory; no allocation) -------------
__device__ float2 g_Xm[BB * CIN * MODES];   // forward modes (+temb bias)
__device__ float2 g_Om[BB * COUT * MODES];  // contracted modes

#define ASTEP (-7.66990393942820615e-4f)    // -2*pi/8192
#define BSTEP (-3.83495196971410307e-4f)    // -2*pi/16384

// ---------------- complex helpers -------------------------------------------
__device__ __forceinline__ float2 cmulf(float2 a, float2 b) {
    return make_float2(fmaf(a.x, b.x, -a.y * b.y), fmaf(a.x, b.y, a.y * b.x));
}
__device__ __forceinline__ float2 caddf(float2 a, float2 b) {
    return make_float2(a.x + b.x, a.y + b.y);
}
__device__ __forceinline__ float2 csubf(float2 a, float2 b) {
    return make_float2(a.x - b.x, a.y - b.y);
}
__device__ __forceinline__ float2 twid(float ang) {
    float s, c;
    __sincosf(ang, &s, &c);
    return make_float2(c, s);
}

// packed fp32x2 fma (FFMA2) — used in the einsum only
__device__ __forceinline__ unsigned long long fma2(unsigned long long a,
                                                   unsigned long long b,
                                                   unsigned long long c) {
    unsigned long long d;
    asm("fma.rn.f32x2 %0, %1, %2, %3;" : "=l"(d) : "l"(a), "l"(b), "l"(c));
    return d;
}

// DFT4 (forward, e^{-2pi i rk/4}), natural-order out
__device__ __forceinline__ void dft4(float2 a, float2 b, float2 c, float2 d, float2 y[4]) {
    float2 t0 = caddf(a, c), t1 = csubf(a, c);
    float2 t2 = caddf(b, d), t3 = csubf(b, d);
    y[0] = caddf(t0, t2);
    y[2] = csubf(t0, t2);
    y[1] = make_float2(t1.x + t3.y, t1.y - t3.x);   // t1 - i*t3
    y[3] = make_float2(t1.x - t3.y, t1.y + t3.x);   // t1 + i*t3
}

// DFT8 (forward), natural-order in/out
__device__ __forceinline__ void fft8(float2 v[8]) {
    const float c = 0.70710678118654752f;
    float2 e[4], o[4];
    dft4(v[0], v[2], v[4], v[6], e);
    dft4(v[1], v[3], v[5], v[7], o);
    float2 o0 = o[0];
    float2 o1 = make_float2(c * (o[1].x + o[1].y), c * (o[1].y - o[1].x)); // *(c,-c)
    float2 o2 = make_float2(o[2].y, -o[2].x);                             // *(-i)
    float2 o3 = make_float2(c * (o[3].y - o[3].x), -c * (o[3].x + o[3].y)); // *(-c,-c)
    v[0] = caddf(e[0], o0);  v[4] = csubf(e[0], o0);
    v[1] = caddf(e[1], o1);  v[5] = csubf(e[1], o1);
    v[2] = caddf(e[2], o2);  v[6] = csubf(e[2], o2);
    v[3] = caddf(e[3], o3);  v[7] = csubf(e[3], o3);
}

// ---- shared stage-1 of DFT16 (4 dft4s + constant twiddles) -----------------
__device__ __forceinline__ void fft16_stage1(const float2 v[16],
                                             float2 y0[4], float2 y1[4],
                                             float2 y2[4], float2 y3[4]) {
    const float c1 = 0.92387953251128675f;   // cos(pi/8)
    const float s1 = 0.38268343236508977f;   // sin(pi/8)
    const float c2 = 0.70710678118654752f;
    dft4(v[0], v[4], v[8],  v[12], y0);
    dft4(v[1], v[5], v[9],  v[13], y1);
    dft4(v[2], v[6], v[10], v[14], y2);
    dft4(v[3], v[7], v[11], v[15], y3);
    y1[1] = cmulf(y1[1], make_float2( c1, -s1));
    y1[2] = cmulf(y1[2], make_float2( c2, -c2));
    y1[3] = cmulf(y1[3], make_float2( s1, -c1));
    y2[1] = cmulf(y2[1], make_float2( c2, -c2));
    y2[2] = make_float2(y2[2].y, -y2[2].x);                 // * (-i)
    y2[3] = cmulf(y2[3], make_float2(-c2, -c2));
    y3[1] = cmulf(y3[1], make_float2( s1, -c1));
    y3[2] = cmulf(y3[2], make_float2(-c2, -c2));
    y3[3] = cmulf(y3[3], make_float2(-c1,  s1));            // W16^9
}

// DFT16 (forward), natural-order in/out; full 16 outputs (inverse path).
__device__ __forceinline__ void fft16(float2 v[16]) {
    float2 y0[4], y1[4], y2[4], y3[4];
    fft16_stage1(v, y0, y1, y2, y3);
    float2 z[4];
    dft4(y0[0], y1[0], y2[0], y3[0], z); v[0]=z[0]; v[4]=z[1]; v[8] =z[2]; v[12]=z[3];
    dft4(y0[1], y1[1], y2[1], y3[1], z); v[1]=z[0]; v[5]=z[1]; v[9] =z[2]; v[13]=z[3];
    dft4(y0[2], y1[2], y2[2], y3[2], z); v[2]=z[0]; v[6]=z[1]; v[10]=z[2]; v[14]=z[3];
    dft4(y0[3], y1[3], y2[3], y3[3], z); v[3]=z[0]; v[7]=z[1]; v[11]=z[2]; v[15]=z[3];
}

// DFT16 pruned for the forward path: only outputs r in {0..3, 12..15}.
// Final dft4 bank emits z0 = t0+t2 and z3 = t1+i*t3 only (6 adds vs 8).
__device__ __forceinline__ void fft16_fwd(float2 v[16]) {
    float2 y0[4], y1[4], y2[4], y3[4];
    fft16_stage1(v, y0, y1, y2, y3);
#pragma unroll
    for (int k = 0; k < 4; k++) {
        float2 t0 = caddf(y0[k], y2[k]), t1 = csubf(y0[k], y2[k]);
        float2 t2 = caddf(y1[k], y3[k]), t3 = csubf(y1[k], y3[k]);
        v[k]      = caddf(t0, t2);
        v[k + 12] = make_float2(t1.x - t3.y, t1.y + t3.x);   // t1 + i*t3
    }
}

// ---- middle radix-8 stages (s = 1, 2) of the 8192-pt Stockham FFT ----------
// Scalar butterflies; twiddles hoisted out of the h loop:
// (tid+512) & (Ns-1) == tid & (Ns-1) for Ns in {8, 64}.
__device__ void fft_stages12(float2* S) {
    const int tid = threadIdx.x;
#pragma unroll
    for (int s = 1; s < 3; s++) {
        const int Ns    = 1 << (3 * s);
        const int shift = 10 - 3 * s;
        const int t = tid & (Ns - 1);
        const float2 w1 = twid((float)(t << shift) * ASTEP);
        const float2 w2 = cmulf(w1, w1);
        const float2 w3 = cmulf(w2, w1);
        const float2 w4 = cmulf(w2, w2);
        const float2 w5 = cmulf(w4, w1);
        const float2 w6 = cmulf(w4, w2);
        const float2 w7 = cmulf(w4, w3);
        float2 v[2][8];
        int base[2];
#pragma unroll
        for (int h = 0; h < 2; h++) {
            const int j = tid + (h << 9);
#pragma unroll
            for (int r = 0; r < 8; r++) v[h][r] = S[IDX(j + (r << 10))];
            v[h][1] = cmulf(v[h][1], w1);
            v[h][2] = cmulf(v[h][2], w2);
            v[h][3] = cmulf(v[h][3], w3);
            v[h][4] = cmulf(v[h][4], w4);
            v[h][5] = cmulf(v[h][5], w5);
            v[h][6] = cmulf(v[h][6], w6);
            v[h][7] = cmulf(v[h][7], w7);
            fft8(v[h]);
            base[h] = ((j >> (3 * s)) << (3 * s + 3)) + t;  // (j/Ns)*8Ns + t
        }
        __syncthreads();
#pragma unroll
        for (int h = 0; h < 2; h++)
#pragma unroll
            for (int r = 0; r < 8; r++)
                S[IDX(base[h] + (r << (3 * s)))] = v[h][r];
        __syncthreads();
    }
}

// ---- final radix-16 load + twiddle (shared by fwd/inv) ---------------------
// w8 computed with its own sincos (parallel MUFU) to break the w1->w2->w4->w8
// dependency chain in this serial region.
__device__ __forceinline__ void radix16_load(const float2* S, int j, float2 v[16]) {
#pragma unroll
    for (int r = 0; r < 16; r++) v[r] = S[IDX(j + (r << 9))];
    const float2 w1 = twid((float)j * ASTEP);
    const float2 w8 = twid((float)(8 * j) * ASTEP);
    const float2 w2 = cmulf(w1, w1);
    const float2 w3 = cmulf(w2, w1);
    const float2 w4 = cmulf(w2, w2);
    const float2 w5 = cmulf(w4, w1);
    const float2 w6 = cmulf(w4, w2);
    const float2 w7 = cmulf(w4, w3);
    v[1]  = cmulf(v[1],  w1);
    v[2]  = cmulf(v[2],  w2);
    v[3]  = cmulf(v[3],  w3);
    v[4]  = cmulf(v[4],  w4);
    v[5]  = cmulf(v[5],  w5);
    v[6]  = cmulf(v[6],  w6);
    v[7]  = cmulf(v[7],  w7);
    v[8]  = cmulf(v[8],  w8);
    v[9]  = cmulf(v[9],  cmulf(w8, w1));
    v[10] = cmulf(v[10], cmulf(w8, w2));
    v[11] = cmulf(v[11], cmulf(w8, w3));
    v[12] = cmulf(v[12], cmulf(w8, w4));
    v[13] = cmulf(v[13], cmulf(w8, w5));
    v[14] = cmulf(v[14], cmulf(w8, w6));
    v[15] = cmulf(v[15], cmulf(w8, w7));
}

// ---------------- kernel: forward rFFT + temb bias (fused) + modes ----------
// Per-CTA bias dot product overlapped with stage-0 gmem loads. Stage 0 reads
// directly from gmem (.cs: read-once). Tail: modes m=tid+512r (r<4) come from
// radix-16 registers (pruned fft16); mirror halves (r>=12) round-trip shared.
__global__ void __launch_bounds__(512, 2)
k_fwd(const float* __restrict__ x, const float* __restrict__ temb,
      const float* __restrict__ dw, const float* __restrict__ db) {
    extern __shared__ float2 sm[];
    float2* S = sm;
    __shared__ float s_part[16];
    __shared__ float s_bias;
    const int row = blockIdx.x;                    // b*64 + c_in
    const int bb  = row >> 6;
    const int cc  = row & 63;
    const float2* xr = (const float2*)x + (size_t)row * NF;
    const int tid = threadIdx.x;

    // ---- bias partial: one product per thread (TEMB == 512 == blockDim) ----
    {
        float tv = __ldg(&temb[bb * TEMB + tid]);
        float act = tv / (1.0f + expf(-tv));       // SiLU
        float prod = act * __ldg(&dw[(size_t)cc * TEMB + tid]);
#pragma unroll
        for (int o = 16; o; o >>= 1) prod += __shfl_xor_sync(0xffffffffu, prod, o);
        if ((tid & 31) == 0) s_part[tid >> 5] = prod;
    }

    // stage 0: Ns=1, twiddle-free, inputs straight from gmem (streaming)
    {
        float2 v[2][8];
#pragma unroll
        for (int h = 0; h < 2; h++) {
            const int j = tid + (h << 9);
#pragma unroll
            for (int r = 0; r < 8; r++) v[h][r] = __ldcs(&xr[j + (r << 10)]);
            fft8(v[h]);
        }
#pragma unroll
        for (int h = 0; h < 2; h++) {
            const int base = (tid + (h << 9)) << 3;
#pragma unroll
            for (int r = 0; r < 8; r++) S[IDX(base + r)] = v[h][r];
        }
        __syncthreads();                           // also publishes s_part
    }
    if (tid == 0) {                                // finish bias reduction
        float sum = __ldg(&db[cc]);
#pragma unroll
        for (int w = 0; w < 16; w++) sum += s_part[w];
        s_bias = sum;                              // read after later barriers
    }
    fft_stages12(S);
    float2 v[16];
    radix16_load(S, tid, v);
    fft16_fwd(v);                                  // only r in {0..3, 12..15}
    __syncthreads();               // stage-2 reads done before overwrite
    // store only the mirror groups r in [12,16): entries 6144..8191
#pragma unroll
    for (int r = 12; r < 16; r++) S[IDX(tid + (r << 9))] = v[r];
    __syncthreads();
    const float tb = s_bias;
    float2* xrow = g_Xm + (size_t)row * MODES;
    // e^{-2pi i m/16384} = e0 * e^{-i pi r/16},  e0 = e^{-2pi i tid/16384}
    const float2 e0 = twid((float)tid * BSTEP);
    const float2 ER[4] = {
        make_float2(1.0f, 0.0f),
        make_float2(0.98078528040323044f, -0.19509032201612827f),
        make_float2(0.92387953251128675f, -0.38268343236508977f),
        make_float2(0.83146961230254524f, -0.55557023301960222f)
    };
#pragma unroll
    for (int r = 0; r < 4; r++) {
        const int m = tid + (r << 9);
        float2 Zm = v[r];
        float2 Zn;
        if (tid == 0) {
            Zn = (r == 0) ? v[0] : v[16 - r];       // Z[8192-512r] is own reg
        } else {
            // 8192-m = (512-tid) + 512*(15-r) -> stored by thread 512-tid
            Zn = S[IDX((512 - tid) + ((15 - r) << 9))];
        }
        float2 A  = make_float2(Zm.x + Zn.x, Zm.y - Zn.y);   // Z + conj(Zn)
        float2 Bc = make_float2(Zm.x - Zn.x, Zm.y + Zn.y);   // Z - conj(Zn)
        float2 C  = cmulf(cmulf(e0, ER[r]), Bc);
        // X = 0.5*A - 0.5*i*C ; add temb bias to real part
        xrow[m] = make_float2(0.5f * (A.x + C.y) + tb, 0.5f * (A.y - C.x));
    }
}

// ---------------- kernel: mode contraction (bim,iom->bom) -------------------
// grid: 256 blocks (8 modes each); block: 256 threads =
//   [bit7]=batch-half x [bits2:7]=32 o-pairs x [bits0:2]=4 mode-pairs.
// Round-8 layout + prefetch.global.L2 at distance 4 (verified winner).
__global__ void __launch_bounds__(256, 2)
k_einsum(const float* __restrict__ wr, const float* __restrict__ wi) {
    extern __shared__ float4 Xc[];                 // [ (b*64+i)*4 + mg ] 64KB
    const int m0  = blockIdx.x * 8;
    const int tid = threadIdx.x;
    for (int idx = tid; idx < BB * CIN * 4; idx += 256) {
        const int p  = idx & 3;
        const int bi = idx >> 2;
        float4 q = *((const float4*)(g_Xm + (size_t)bi * MODES + m0) + p);
        Xc[idx] = make_float4(q.x, q.z, q.y, q.w); // (re0, re1, im0, im1)
    }
    __syncthreads();
    const int mg = tid & 3;
    const int op = (tid >> 2) & 31;
    const int bh = tid >> 7;
    const int o0 = 2 * op;
    const int m  = m0 + 2 * mg;
    const int b0 = bh * 8;

    unsigned long long ar[2][8], ai[2][8];
#pragma unroll
    for (int k = 0; k < 2; k++)
#pragma unroll
        for (int b = 0; b < 8; b++) { ar[k][b] = 0ULL; ai[k][b] = 0ULL; }

    const size_t istep = (size_t)COUT * MODES;
    size_t off = (size_t)o0 * MODES + m;
    unsigned long long cwr0 = *(const unsigned long long*)(wr + off);
    unsigned long long cwr1 = *(const unsigned long long*)(wr + off + MODES);
    unsigned long long cwi0 = *(const unsigned long long*)(wi + off);
    unsigned long long cwi1 = *(const unsigned long long*)(wi + off + MODES);

    for (int i = 0; i < CIN; i++) {
        unsigned long long nwr0, nwr1, nwi0, nwi1;
        if (i + 1 < CIN) {                          // register prefetch, d=1
            const size_t noff = off + istep;
            nwr0 = *(const unsigned long long*)(wr + noff);
            nwr1 = *(const unsigned long long*)(wr + noff + MODES);
            nwi0 = *(const unsigned long long*)(wi + noff);
            nwi1 = *(const unsigned long long*)(wi + noff + MODES);
        }
        if (i + 4 < CIN) {                          // L2 prefetch, distance 4
            const size_t poff = off + 4 * istep;
            asm volatile("prefetch.global.L2 [%0];" :: "l"(wr + poff));
            asm volatile("prefetch.global.L2 [%0];" :: "l"(wr + poff + MODES));
            asm volatile("prefetch.global.L2 [%0];" :: "l"(wi + poff));
            asm volatile("prefetch.global.L2 [%0];" :: "l"(wi + poff + MODES));
        }
#pragma unroll
        for (int b = 0; b < 8; b++) {
            const int idx2 = ((b0 + b) * CIN + i) * 4 + mg;
            const ulonglong2 xu = *(const ulonglong2*)(Xc + idx2); // 1 LDS.128
            const unsigned long long xr2  = xu.x;                  // (re0,re1)
            const unsigned long long xi2  = xu.y;                  // (im0,im1)
            const unsigned long long xin2 = xi2 ^ 0x8000000080000000ULL;
            ar[0][b] = fma2(xr2,  cwr0, ar[0][b]);
            ar[0][b] = fma2(xin2, cwi0, ar[0][b]);
            ai[0][b] = fma2(xr2,  cwi0, ai[0][b]);
            ai[0][b] = fma2(xi2,  cwr0, ai[0][b]);
            ar[1][b] = fma2(xr2,  cwr1, ar[1][b]);
            ar[1][b] = fma2(xin2, cwi1, ar[1][b]);
            ai[1][b] = fma2(xr2,  cwi1, ai[1][b]);
            ai[1][b] = fma2(xi2,  cwr1, ai[1][b]);
        }
        cwr0 = nwr0; cwr1 = nwr1; cwi0 = nwi0; cwi1 = nwi1;
        off += istep;
    }
#pragma unroll
    for (int k = 0; k < 2; k++)
#pragma unroll
        for (int b = 0; b < 8; b++) {
            float r0, r1, i0, i1;
            asm("mov.b64 {%0, %1}, %2;" : "=f"(r0), "=f"(r1) : "l"(ar[k][b]));
            asm("mov.b64 {%0, %1}, %2;" : "=f"(i0), "=f"(i1) : "l"(ai[k][b]));
            const size_t ob = ((size_t)((b0 + b) * COUT + o0 + k)) * MODES + m;
            *((float4*)(g_Om + ob)) = make_float4(r0, i0, r1, i1);
        }
}

// ---------------- kernel: inverse rFFT --------------------------------------
// Stage 0 builds the Hermitian-packed spectrum in REGISTERS from g_Om
// (only r in {0,1,6,7} nonzero); final radix-16 writes straight to gmem (.cs).
// Stage-0 twiddles: ONE sincos total; h=1 base derived by constant rotation
// e^{-i pi/16}; r-factors are constant rotations e^{-i pi r/8}.
__global__ void __launch_bounds__(512, 2)
k_inv(float* __restrict__ out) {
    extern __shared__ float2 sm[];
    float2* S = sm;
    const int row = blockIdx.x;                    // b*64 + c_out
    const float2* orow = g_Om + (size_t)row * MODES;
    const int tid = threadIdx.x;
    // stage 0 (Ns=1, twiddle-free): inputs computed inline
    {
        const float2 eb = twid((float)tid * BSTEP);    // e^{-2pi i tid/16384}
        float2 v[2][8];
#pragma unroll
        for (int h = 0; h < 2; h++) {
            const int j = tid + (h << 9);
            // e0 = e^{-2pi i j/16384}; h=1 multiplies by e^{-i pi/16}
            const float2 e0 = (h == 0) ? eb
                : cmulf(eb, make_float2(0.98078528040323044f, -0.19509032201612827f));
#pragma unroll
            for (int r = 0; r < 8; r++) {
                if (r >= 2 && r <= 5) { v[h][r] = make_float2(0.0f, 0.0f); continue; }
                const int mm = j + (r << 10);
                float2 Xm = make_float2(0.0f, 0.0f);
                float2 Cc = make_float2(0.0f, 0.0f);
                if (r < 2) {                       // mm < 2048
                    Xm = __ldg(&orow[mm]);
                    if (mm == 0) Xm.y = 0.0f;      // irfft drops Im(X[0])
                } else {                           // r>=6: mirror branch
                    const int mr = NF - mm;
                    if (mr < MODES) {
                        float2 q = __ldg(&orow[mr]);
                        Cc = make_float2(q.x, -q.y);
                    }
                }
                float2 Ze = make_float2(0.5f * (Xm.x + Cc.x), 0.5f * (Xm.y + Cc.y));
                float2 D  = make_float2(0.5f * (Xm.x - Cc.x), 0.5f * (Xm.y - Cc.y));
                // e = e0 * e^{-i pi r/8} (constants for r in {0,1,6,7})
                float2 er;
                if (r == 0)      er = e0;
                else if (r == 1) er = cmulf(e0, make_float2( 0.92387953251128675f, -0.38268343236508977f));
                else if (r == 6) er = cmulf(e0, make_float2(-0.70710678118654752f, -0.70710678118654752f));
                else             er = cmulf(e0, make_float2(-0.92387953251128675f, -0.38268343236508977f));
                float2 Zo = cmulf(make_float2(er.x, -er.y), D);
                // Z = Ze + i*Zo ; store conj(Z) so forward FFT computes inverse
                v[h][r] = make_float2(Ze.x - Zo.y, -(Ze.y + Zo.x));
            }
            fft8(v[h]);
        }
#pragma unroll
        for (int h = 0; h < 2; h++) {
            const int base = (tid + (h << 9)) << 3;
#pragma unroll
            for (int r = 0; r < 8; r++) S[IDX(base + r)] = v[h][r];
        }
        __syncthreads();
    }
    fft_stages12(S);
    // final radix-16: write results straight to gmem (index j + 512r)
    {
        float2 v[16];
        radix16_load(S, tid, v);
        fft16(v);
        const float sc = 1.0f / 8192.0f;
        float2* outr = (float2*)out + (size_t)row * NF;
#pragma unroll
        for (int r = 0; r < 16; r++) {
            float2 z = v[r];
            __stcs(&outr[tid + (r << 9)],
                   make_float2(z.x * sc, -z.y * sc));   // conj + 1/N, streaming
        }
    }
}

// ---------------- launch ----------------------------------------------------
extern "C" void kernel_launch(void* const* d_in, const int* in_sizes, int n_in,
                              void* d_out, int out_size) {
    const float* x    = (const float*)d_in[0];
    const float* temb = (const float*)d_in[1];
    const float* wr   = (const float*)d_in[2];
    const float* wi   = (const float*)d_in[3];
    const float* dw   = (const float*)d_in[4];
    const float* db   = (const float*)d_in[5];
    float* out = (float*)d_out;

    cudaFuncSetAttribute(k_fwd,    cudaFuncAttributeMaxDynamicSharedMemorySize, SBUF * 8);
    cudaFuncSetAttribute(k_inv,    cudaFuncAttributeMaxDynamicSharedMemorySize, SBUF * 8);
    cudaFuncSetAttribute(k_einsum, cudaFuncAttributeMaxDynamicSharedMemorySize, 65536);

    k_fwd   <<<BB * CIN, 512, SBUF * 8>>>(x, temb, dw, db);
    k_einsum<<<MODES / 8, 256, 65536>>>(wr, wi);
    k_inv   <<<BB * COUT, 512, SBUF * 8>>>(out);
}

// round 16
// speedup vs baseline: 1.0330x; 1.0120x over previous
#include <cuda_runtime.h>
#include <math.h>

#define BB    16
#define CIN   64
#define COUT  64
#define NN    16384
#define NF    8192      // complex FFT size (N/2)
#define MODES 2048
#define TEMB  512

// Skewed shared index: every 8 complexes insert 1 pad -> tames smem bank
// conflicts of the strided Stockham stores.
#define IDX(a) ((a) + ((a) >> 3))
#define SBUF   9216      // IDX(8191)=9214 < 9216  -> 73728 bytes (single buffer)

// ---------------- scratch (static device memory; no allocation) -------------
__device__ float2 g_Xm[BB * CIN * MODES];   // forward modes (+temb bias)
__device__ float2 g_Om[BB * COUT * MODES];  // contracted modes

#define ASTEP (-7.66990393942820615e-4f)    // -2*pi/8192
#define BSTEP (-3.83495196971410307e-4f)    // -2*pi/16384

// ---------------- complex helpers -------------------------------------------
__device__ __forceinline__ float2 cmulf(float2 a, float2 b) {
    return make_float2(fmaf(a.x, b.x, -a.y * b.y), fmaf(a.x, b.y, a.y * b.x));
}
__device__ __forceinline__ float2 caddf(float2 a, float2 b) {
    return make_float2(a.x + b.x, a.y + b.y);
}
__device__ __forceinline__ float2 csubf(float2 a, float2 b) {
    return make_float2(a.x - b.x, a.y - b.y);
}
__device__ __forceinline__ float2 twid(float ang) {
    float s, c;
    __sincosf(ang, &s, &c);
    return make_float2(c, s);
}

// packed fp32x2 fma (FFMA2) — used in the einsum only
__device__ __forceinline__ unsigned long long fma2(unsigned long long a,
                                                   unsigned long long b,
                                                   unsigned long long c) {
    unsigned long long d;
    asm("fma.rn.f32x2 %0, %1, %2, %3;" : "=l"(d) : "l"(a), "l"(b), "l"(c));
    return d;
}

// DFT4 (forward, e^{-2pi i rk/4}), natural-order out
__device__ __forceinline__ void dft4(float2 a, float2 b, float2 c, float2 d, float2 y[4]) {
    float2 t0 = caddf(a, c), t1 = csubf(a, c);
    float2 t2 = caddf(b, d), t3 = csubf(b, d);
    y[0] = caddf(t0, t2);
    y[2] = csubf(t0, t2);
    y[1] = make_float2(t1.x + t3.y, t1.y - t3.x);   // t1 - i*t3
    y[3] = make_float2(t1.x - t3.y, t1.y + t3.x);   // t1 + i*t3
}

// DFT8 (forward), natural-order in/out
__device__ __forceinline__ void fft8(float2 v[8]) {
    const float c = 0.70710678118654752f;
    float2 e[4], o[4];
    dft4(v[0], v[2], v[4], v[6], e);
    dft4(v[1], v[3], v[5], v[7], o);
    float2 o0 = o[0];
    float2 o1 = make_float2(c * (o[1].x + o[1].y), c * (o[1].y - o[1].x)); // *(c,-c)
    float2 o2 = make_float2(o[2].y, -o[2].x);                             // *(-i)
    float2 o3 = make_float2(c * (o[3].y - o[3].x), -c * (o[3].x + o[3].y)); // *(-c,-c)
    v[0] = caddf(e[0], o0);  v[4] = csubf(e[0], o0);
    v[1] = caddf(e[1], o1);  v[5] = csubf(e[1], o1);
    v[2] = caddf(e[2], o2);  v[6] = csubf(e[2], o2);
    v[3] = caddf(e[3], o3);  v[7] = csubf(e[3], o3);
}

// ---- shared stage-1 of DFT16 (4 dft4s + constant twiddles) -----------------
__device__ __forceinline__ void fft16_stage1(const float2 v[16],
                                             float2 y0[4], float2 y1[4],
                                             float2 y2[4], float2 y3[4]) {
    const float c1 = 0.92387953251128675f;   // cos(pi/8)
    const float s1 = 0.38268343236508977f;   // sin(pi/8)
    const float c2 = 0.70710678118654752f;
    dft4(v[0], v[4], v[8],  v[12], y0);
    dft4(v[1], v[5], v[9],  v[13], y1);
    dft4(v[2], v[6], v[10], v[14], y2);
    dft4(v[3], v[7], v[11], v[15], y3);
    y1[1] = cmulf(y1[1], make_float2( c1, -s1));
    y1[2] = cmulf(y1[2], make_float2( c2, -c2));
    y1[3] = cmulf(y1[3], make_float2( s1, -c1));
    y2[1] = cmulf(y2[1], make_float2( c2, -c2));
    y2[2] = make_float2(y2[2].y, -y2[2].x);                 // * (-i)
    y2[3] = cmulf(y2[3], make_float2(-c2, -c2));
    y3[1] = cmulf(y3[1], make_float2( s1, -c1));
    y3[2] = cmulf(y3[2], make_float2(-c2, -c2));
    y3[3] = cmulf(y3[3], make_float2(-c1,  s1));            // W16^9
}

// DFT16 (forward), natural-order in/out; full 16 outputs (inverse path).
__device__ __forceinline__ void fft16(float2 v[16]) {
    float2 y0[4], y1[4], y2[4], y3[4];
    fft16_stage1(v, y0, y1, y2, y3);
    float2 z[4];
    dft4(y0[0], y1[0], y2[0], y3[0], z); v[0]=z[0]; v[4]=z[1]; v[8] =z[2]; v[12]=z[3];
    dft4(y0[1], y1[1], y2[1], y3[1], z); v[1]=z[0]; v[5]=z[1]; v[9] =z[2]; v[13]=z[3];
    dft4(y0[2], y1[2], y2[2], y3[2], z); v[2]=z[0]; v[6]=z[1]; v[10]=z[2]; v[14]=z[3];
    dft4(y0[3], y1[3], y2[3], y3[3], z); v[3]=z[0]; v[7]=z[1]; v[11]=z[2]; v[15]=z[3];
}

// DFT16 pruned for the forward path: only outputs r in {0..3, 12..15}.
// Final dft4 bank emits z0 = t0+t2 and z3 = t1+i*t3 only (6 adds vs 8).
__device__ __forceinline__ void fft16_fwd(float2 v[16]) {
    float2 y0[4], y1[4], y2[4], y3[4];
    fft16_stage1(v, y0, y1, y2, y3);
#pragma unroll
    for (int k = 0; k < 4; k++) {
        float2 t0 = caddf(y0[k], y2[k]), t1 = csubf(y0[k], y2[k]);
        float2 t2 = caddf(y1[k], y3[k]), t3 = csubf(y1[k], y3[k]);
        v[k]      = caddf(t0, t2);
        v[k + 12] = make_float2(t1.x - t3.y, t1.y + t3.x);   // t1 + i*t3
    }
}

// ---- vectorized stage-0 store: butterflies j0=2*tid, j1=2*tid+1 ------------
// Outputs land at skewed addresses 18t..18t+7 and 18t+9..18t+16: two
// contiguous runs -> 7 STS.128 + 2 STS.64, conflict-free phases.
__device__ __forceinline__ void stage0_store(float2* S, int tid,
                                             const float2 v0[8], const float2 v1[8]) {
    float4* S4 = (float4*)S;
    const int t9  = 9 * tid;         // float4 index of skewed 18*tid
    const int t18 = 18 * tid;
    S4[t9 + 0] = make_float4(v0[0].x, v0[0].y, v0[1].x, v0[1].y);
    S4[t9 + 1] = make_float4(v0[2].x, v0[2].y, v0[3].x, v0[3].y);
    S4[t9 + 2] = make_float4(v0[4].x, v0[4].y, v0[5].x, v0[5].y);
    S4[t9 + 3] = make_float4(v0[6].x, v0[6].y, v0[7].x, v0[7].y);
    S[t18 + 9] = v1[0];
    S4[t9 + 5] = make_float4(v1[1].x, v1[1].y, v1[2].x, v1[2].y);
    S4[t9 + 6] = make_float4(v1[3].x, v1[3].y, v1[4].x, v1[4].y);
    S4[t9 + 7] = make_float4(v1[5].x, v1[5].y, v1[6].x, v1[6].y);
    S[t18 + 16] = v1[7];
}

// ---- middle radix-8 stages (s = 1, 2) of the 8192-pt Stockham FFT ----------
// Scalar butterflies; twiddles hoisted out of the h loop:
// (tid+512) & (Ns-1) == tid & (Ns-1) for Ns in {8, 64}.
__device__ void fft_stages12(float2* S) {
    const int tid = threadIdx.x;
#pragma unroll
    for (int s = 1; s < 3; s++) {
        const int Ns    = 1 << (3 * s);
        const int shift = 10 - 3 * s;
        const int t = tid & (Ns - 1);
        const float2 w1 = twid((float)(t << shift) * ASTEP);
        const float2 w2 = cmulf(w1, w1);
        const float2 w3 = cmulf(w2, w1);
        const float2 w4 = cmulf(w2, w2);
        const float2 w5 = cmulf(w4, w1);
        const float2 w6 = cmulf(w4, w2);
        const float2 w7 = cmulf(w4, w3);
        float2 v[2][8];
        int base[2];
#pragma unroll
        for (int h = 0; h < 2; h++) {
            const int j = tid + (h << 9);
#pragma unroll
            for (int r = 0; r < 8; r++) v[h][r] = S[IDX(j + (r << 10))];
            v[h][1] = cmulf(v[h][1], w1);
            v[h][2] = cmulf(v[h][2], w2);
            v[h][3] = cmulf(v[h][3], w3);
            v[h][4] = cmulf(v[h][4], w4);
            v[h][5] = cmulf(v[h][5], w5);
            v[h][6] = cmulf(v[h][6], w6);
            v[h][7] = cmulf(v[h][7], w7);
            fft8(v[h]);
            base[h] = ((j >> (3 * s)) << (3 * s + 3)) + t;  // (j/Ns)*8Ns + t
        }
        __syncthreads();
#pragma unroll
        for (int h = 0; h < 2; h++)
#pragma unroll
            for (int r = 0; r < 8; r++)
                S[IDX(base[h] + (r << (3 * s)))] = v[h][r];
        __syncthreads();
    }
}

// ---- final radix-16 load + twiddle (shared by fwd/inv) ---------------------
__device__ __forceinline__ void radix16_load(const float2* S, int j, float2 v[16]) {
#pragma unroll
    for (int r = 0; r < 16; r++) v[r] = S[IDX(j + (r << 9))];
    const float2 w1 = twid((float)j * ASTEP);
    const float2 w2 = cmulf(w1, w1);
    const float2 w3 = cmulf(w2, w1);
    const float2 w4 = cmulf(w2, w2);
    const float2 w5 = cmulf(w4, w1);
    const float2 w6 = cmulf(w4, w2);
    const float2 w7 = cmulf(w4, w3);
    const float2 w8 = cmulf(w4, w4);
    v[1]  = cmulf(v[1],  w1);
    v[2]  = cmulf(v[2],  w2);
    v[3]  = cmulf(v[3],  w3);
    v[4]  = cmulf(v[4],  w4);
    v[5]  = cmulf(v[5],  w5);
    v[6]  = cmulf(v[6],  w6);
    v[7]  = cmulf(v[7],  w7);
    v[8]  = cmulf(v[8],  w8);
    v[9]  = cmulf(v[9],  cmulf(w8, w1));
    v[10] = cmulf(v[10], cmulf(w8, w2));
    v[11] = cmulf(v[11], cmulf(w8, w3));
    v[12] = cmulf(v[12], cmulf(w8, w4));
    v[13] = cmulf(v[13], cmulf(w8, w5));
    v[14] = cmulf(v[14], cmulf(w8, w6));
    v[15] = cmulf(v[15], cmulf(w8, w7));
}

// ---------------- kernel: forward rFFT + temb bias (fused) + modes ----------
// Per-CTA bias dot product overlapped with stage-0 gmem loads. Stage 0:
// paired butterflies (2tid, 2tid+1) -> float4 gmem loads + vectorized stores.
// Tail: modes m=tid+512r (r<4) come from radix-16 registers (pruned fft16);
// mirror halves (r>=12) round-trip shared.
__global__ void __launch_bounds__(512, 2)
k_fwd(const float* __restrict__ x, const float* __restrict__ temb,
      const float* __restrict__ dw, const float* __restrict__ db) {
    extern __shared__ float2 sm[];
    float2* S = sm;
    __shared__ float s_part[16];
    __shared__ float s_bias;
    const int row = blockIdx.x;                    // b*64 + c_in
    const int bb  = row >> 6;
    const int cc  = row & 63;
    const float4* xr4 = (const float4*)(x + (size_t)row * NN);
    const int tid = threadIdx.x;

    // ---- bias partial: one product per thread (TEMB == 512 == blockDim) ----
    {
        float tv = __ldg(&temb[bb * TEMB + tid]);
        float act = tv / (1.0f + expf(-tv));       // SiLU
        float prod = act * __ldg(&dw[(size_t)cc * TEMB + tid]);
#pragma unroll
        for (int o = 16; o; o >>= 1) prod += __shfl_xor_sync(0xffffffffu, prod, o);
        if ((tid & 31) == 0) s_part[tid >> 5] = prod;
    }

    // stage 0: Ns=1, twiddle-free, paired butterflies, float4 streaming loads
    {
        float2 v[2][8];
#pragma unroll
        for (int r = 0; r < 8; r++) {
            float4 q = __ldcs(&xr4[tid + (r << 9)]);  // complexes 2tid, 2tid+1
            v[0][r] = make_float2(q.x, q.y);
            v[1][r] = make_float2(q.z, q.w);
        }
        fft8(v[0]);
        fft8(v[1]);
        stage0_store(S, tid, v[0], v[1]);
        __syncthreads();                           // also publishes s_part
    }
    if (tid == 0) {                                // finish bias reduction
        float sum = __ldg(&db[cc]);
#pragma unroll
        for (int w = 0; w < 16; w++) sum += s_part[w];
        s_bias = sum;                              // read after later barriers
    }
    fft_stages12(S);
    float2 v[16];
    radix16_load(S, tid, v);
    fft16_fwd(v);                                  // only r in {0..3, 12..15}
    __syncthreads();               // stage-2 reads done before overwrite
    // store only the mirror groups r in [12,16): entries 6144..8191
#pragma unroll
    for (int r = 12; r < 16; r++) S[IDX(tid + (r << 9))] = v[r];
    __syncthreads();
    const float tb = s_bias;
    float2* xrow = g_Xm + (size_t)row * MODES;
    // e^{-2pi i m/16384} = e0 * e^{-i pi r/16},  e0 = e^{-2pi i tid/16384}
    const float2 e0 = twid((float)tid * BSTEP);
    const float2 ER[4] = {
        make_float2(1.0f, 0.0f),
        make_float2(0.98078528040323044f, -0.19509032201612827f),
        make_float2(0.92387953251128675f, -0.38268343236508977f),
        make_float2(0.83146961230254524f, -0.55557023301960222f)
    };
#pragma unroll
    for (int r = 0; r < 4; r++) {
        const int m = tid + (r << 9);
        float2 Zm = v[r];
        float2 Zn;
        if (tid == 0) {
            Zn = (r == 0) ? v[0] : v[16 - r];       // Z[8192-512r] is own reg
        } else {
            // 8192-m = (512-tid) + 512*(15-r) -> stored by thread 512-tid
            Zn = S[IDX((512 - tid) + ((15 - r) << 9))];
        }
        float2 A  = make_float2(Zm.x + Zn.x, Zm.y - Zn.y);   // Z + conj(Zn)
        float2 Bc = make_float2(Zm.x - Zn.x, Zm.y + Zn.y);   // Z - conj(Zn)
        float2 C  = cmulf(cmulf(e0, ER[r]), Bc);
        // X = 0.5*A - 0.5*i*C ; add temb bias to real part
        xrow[m] = make_float2(0.5f * (A.x + C.y) + tb, 0.5f * (A.y - C.x));
    }
}

// ---------------- kernel: mode contraction (bim,iom->bom) -------------------
// grid: 256 blocks (8 modes each); block: 256 threads =
//   [bit7]=batch-half x [bits2:7]=32 o-pairs x [bits0:2]=4 mode-pairs.
// Round-8 layout + prefetch.global.L2 at distance 4 (verified winner).
__global__ void __launch_bounds__(256, 2)
k_einsum(const float* __restrict__ wr, const float* __restrict__ wi) {
    extern __shared__ float4 Xc[];                 // [ (b*64+i)*4 + mg ] 64KB
    const int m0  = blockIdx.x * 8;
    const int tid = threadIdx.x;
    for (int idx = tid; idx < BB * CIN * 4; idx += 256) {
        const int p  = idx & 3;
        const int bi = idx >> 2;
        float4 q = *((const float4*)(g_Xm + (size_t)bi * MODES + m0) + p);
        Xc[idx] = make_float4(q.x, q.z, q.y, q.w); // (re0, re1, im0, im1)
    }
    __syncthreads();
    const int mg = tid & 3;
    const int op = (tid >> 2) & 31;
    const int bh = tid >> 7;
    const int o0 = 2 * op;
    const int m  = m0 + 2 * mg;
    const int b0 = bh * 8;

    unsigned long long ar[2][8], ai[2][8];
#pragma unroll
    for (int k = 0; k < 2; k++)
#pragma unroll
        for (int b = 0; b < 8; b++) { ar[k][b] = 0ULL; ai[k][b] = 0ULL; }

    const size_t istep = (size_t)COUT * MODES;
    size_t off = (size_t)o0 * MODES + m;
    unsigned long long cwr0 = *(const unsigned long long*)(wr + off);
    unsigned long long cwr1 = *(const unsigned long long*)(wr + off + MODES);
    unsigned long long cwi0 = *(const unsigned long long*)(wi + off);
    unsigned long long cwi1 = *(const unsigned long long*)(wi + off + MODES);

    for (int i = 0; i < CIN; i++) {
        unsigned long long nwr0, nwr1, nwi0, nwi1;
        if (i + 1 < CIN) {                          // register prefetch, d=1
            const size_t noff = off + istep;
            nwr0 = *(const unsigned long long*)(wr + noff);
            nwr1 = *(const unsigned long long*)(wr + noff + MODES);
            nwi0 = *(const unsigned long long*)(wi + noff);
            nwi1 = *(const unsigned long long*)(wi + noff + MODES);
        }
        if (i + 4 < CIN) {                          // L2 prefetch, distance 4
            const size_t poff = off + 4 * istep;
            asm volatile("prefetch.global.L2 [%0];" :: "l"(wr + poff));
            asm volatile("prefetch.global.L2 [%0];" :: "l"(wr + poff + MODES));
            asm volatile("prefetch.global.L2 [%0];" :: "l"(wi + poff));
            asm volatile("prefetch.global.L2 [%0];" :: "l"(wi + poff + MODES));
        }
#pragma unroll
        for (int b = 0; b < 8; b++) {
            const int idx2 = ((b0 + b) * CIN + i) * 4 + mg;
            const ulonglong2 xu = *(const ulonglong2*)(Xc + idx2); // 1 LDS.128
            const unsigned long long xr2  = xu.x;                  // (re0,re1)
            const unsigned long long xi2  = xu.y;                  // (im0,im1)
            const unsigned long long xin2 = xi2 ^ 0x8000000080000000ULL;
            ar[0][b] = fma2(xr2,  cwr0, ar[0][b]);
            ar[0][b] = fma2(xin2, cwi0, ar[0][b]);
            ai[0][b] = fma2(xr2,  cwi0, ai[0][b]);
            ai[0][b] = fma2(xi2,  cwr0, ai[0][b]);
            ar[1][b] = fma2(xr2,  cwr1, ar[1][b]);
            ar[1][b] = fma2(xin2, cwi1, ar[1][b]);
            ai[1][b] = fma2(xr2,  cwi1, ai[1][b]);
            ai[1][b] = fma2(xi2,  cwr1, ai[1][b]);
        }
        cwr0 = nwr0; cwr1 = nwr1; cwi0 = nwi0; cwi1 = nwi1;
        off += istep;
    }
#pragma unroll
    for (int k = 0; k < 2; k++)
#pragma unroll
        for (int b = 0; b < 8; b++) {
            float r0, r1, i0, i1;
            asm("mov.b64 {%0, %1}, %2;" : "=f"(r0), "=f"(r1) : "l"(ar[k][b]));
            asm("mov.b64 {%0, %1}, %2;" : "=f"(i0), "=f"(i1) : "l"(ai[k][b]));
            const size_t ob = ((size_t)((b0 + b) * COUT + o0 + k)) * MODES + m;
            *((float4*)(g_Om + ob)) = make_float4(r0, i0, r1, i1);
        }
}

// ---------------- kernel: inverse rFFT --------------------------------------
// Stage 0 builds the Hermitian-packed spectrum in REGISTERS from g_Om with
// paired butterflies (2tid, 2tid+1): direct loads as float4, vectorized
// stores; one sincos per butterfly (MUFU has slack). Final radix-16 writes
// straight to gmem (.cs).
__global__ void __launch_bounds__(512, 2)
k_inv(float* __restrict__ out) {
    extern __shared__ float2 sm[];
    float2* S = sm;
    const int row = blockIdx.x;                    // b*64 + c_out
    const float2* orow = g_Om + (size_t)row * MODES;
    const int tid = threadIdx.x;
    // stage 0 (Ns=1, twiddle-free): inputs computed inline
    {
        const float4* orow4 = (const float4*)orow;
        const int j0 = 2 * tid;
        const float2 e0b[2] = { twid((float)j0 * BSTEP),
                                twid((float)(j0 + 1) * BSTEP) };
        float2 v[2][8];
#pragma unroll
        for (int b = 0; b < 2; b++)
#pragma unroll
            for (int r = 2; r < 6; r++) v[b][r] = make_float2(0.0f, 0.0f);

#pragma unroll
        for (int r = 0; r < 8; r++) {
            if (r >= 2 && r <= 5) continue;
            float2 Xm[2], Cc[2];
            Xm[0] = Xm[1] = Cc[0] = Cc[1] = make_float2(0.0f, 0.0f);
            if (r < 2) {                           // direct: orow[j0+1024r], +1
                float4 q = __ldg(&orow4[tid + (r << 9)]);
                Xm[0] = make_float2(q.x, q.y);
                Xm[1] = make_float2(q.z, q.w);
                if (r == 0 && tid == 0) Xm[0].y = 0.0f;  // irfft drops Im(X[0])
            } else {                               // mirror: mr0 = 8192-(j0+1024r)
                const int mr0 = NF - (j0 + (r << 10));
                float2 q1 = __ldg(&orow[mr0 - 1]); // always < MODES
                Cc[1] = make_float2(q1.x, -q1.y);
                if (mr0 < MODES) {                 // false only for r=6, tid=0
                    float2 q0 = __ldg(&orow[mr0]);
                    Cc[0] = make_float2(q0.x, -q0.y);
                }
            }
#pragma unroll
            for (int b = 0; b < 2; b++) {
                // e = e0 * e^{-i pi r/8} (constants for r in {0,1,6,7})
                float2 er;
                if (r == 0)      er = e0b[b];
                else if (r == 1) er = cmulf(e0b[b], make_float2( 0.92387953251128675f, -0.38268343236508977f));
                else if (r == 6) er = cmulf(e0b[b], make_float2(-0.70710678118654752f, -0.70710678118654752f));
                else             er = cmulf(e0b[b], make_float2(-0.92387953251128675f, -0.38268343236508977f));
                float2 Ze = make_float2(0.5f * (Xm[b].x + Cc[b].x), 0.5f * (Xm[b].y + Cc[b].y));
                float2 D  = make_float2(0.5f * (Xm[b].x - Cc[b].x), 0.5f * (Xm[b].y - Cc[b].y));
                float2 Zo = cmulf(make_float2(er.x, -er.y), D);
                // Z = Ze + i*Zo ; store conj(Z) so forward FFT computes inverse
                v[b][r] = make_float2(Ze.x - Zo.y, -(Ze.y + Zo.x));
            }
        }
        fft8(v[0]);
        fft8(v[1]);
        stage0_store(S, tid, v[0], v[1]);
        __syncthreads();
    }
    fft_stages12(S);
    // final radix-16: write results straight to gmem (index j + 512r)
    {
        float2 v[16];
        radix16_load(S, tid, v);
        fft16(v);
        const float sc = 1.0f / 8192.0f;
        float2* outr = (float2*)out + (size_t)row * NF;
#pragma unroll
        for (int r = 0; r < 16; r++) {
            float2 z = v[r];
            __stcs(&outr[tid + (r << 9)],
                   make_float2(z.x * sc, -z.y * sc));   // conj + 1/N, streaming
        }
    }
}

// ---------------- launch ----------------------------------------------------
extern "C" void kernel_launch(void* const* d_in, const int* in_sizes, int n_in,
                              void* d_out, int out_size) {
    const float* x    = (const float*)d_in[0];
    const float* temb = (const float*)d_in[1];
    const float* wr   = (const float*)d_in[2];
    const float* wi   = (const float*)d_in[3];
    const float* dw   = (const float*)d_in[4];
    const float* db   = (const float*)d_in[5];
    float* out = (float*)d_out;

    cudaFuncSetAttribute(k_fwd,    cudaFuncAttributeMaxDynamicSharedMemorySize, SBUF * 8);
    cudaFuncSetAttribute(k_inv,    cudaFuncAttributeMaxDynamicSharedMemorySize, SBUF * 8);
    cudaFuncSetAttribute(k_einsum, cudaFuncAttributeMaxDynamicSharedMemorySize, 65536);

    k_fwd   <<<BB * CIN, 512, SBUF * 8>>>(x, temb, dw, db);
    k_einsum<<<MODES / 8, 256, 65536>>>(wr, wi);
    k_inv   <<<BB * COUT, 512, SBUF * 8>>>(out);
}

// round 17
// speedup vs baseline: 1.0472x; 1.0138x over previous
#include <cuda_runtime.h>
#include <math.h>

#define BB    16
#define CIN   64
#define COUT  64
#define NN    16384
#define NF    8192      // complex FFT size (N/2)
#define MODES 2048
#define TEMB  512

// Skewed shared index: every 8 complexes insert 1 pad -> tames smem bank
// conflicts of the strided Stockham stores.
#define IDX(a) ((a) + ((a) >> 3))
#define SBUF   9216      // IDX(8191)=9214 < 9216  -> 73728 bytes (single buffer)
#define FWD_SMEM ((SBUF + 2048) * 8)   // S + disjoint mirror buffer M (16KB)

// ---------------- scratch (static device memory; no allocation) -------------
__device__ float2 g_Xm[BB * CIN * MODES];   // forward modes (+temb bias)
__device__ float2 g_Om[BB * COUT * MODES];  // contracted modes

#define ASTEP (-7.66990393942820615e-4f)    // -2*pi/8192
#define BSTEP (-3.83495196971410307e-4f)    // -2*pi/16384

// ---------------- complex helpers -------------------------------------------
__device__ __forceinline__ float2 cmulf(float2 a, float2 b) {
    return make_float2(fmaf(a.x, b.x, -a.y * b.y), fmaf(a.x, b.y, a.y * b.x));
}
__device__ __forceinline__ float2 caddf(float2 a, float2 b) {
    return make_float2(a.x + b.x, a.y + b.y);
}
__device__ __forceinline__ float2 csubf(float2 a, float2 b) {
    return make_float2(a.x - b.x, a.y - b.y);
}
__device__ __forceinline__ float2 twid(float ang) {
    float s, c;
    __sincosf(ang, &s, &c);
    return make_float2(c, s);
}

// packed fp32x2 fma (FFMA2) — used in the einsum only
__device__ __forceinline__ unsigned long long fma2(unsigned long long a,
                                                   unsigned long long b,
                                                   unsigned long long c) {
    unsigned long long d;
    asm("fma.rn.f32x2 %0, %1, %2, %3;" : "=l"(d) : "l"(a), "l"(b), "l"(c));
    return d;
}

// DFT4 (forward, e^{-2pi i rk/4}), natural-order out
__device__ __forceinline__ void dft4(float2 a, float2 b, float2 c, float2 d, float2 y[4]) {
    float2 t0 = caddf(a, c), t1 = csubf(a, c);
    float2 t2 = caddf(b, d), t3 = csubf(b, d);
    y[0] = caddf(t0, t2);
    y[2] = csubf(t0, t2);
    y[1] = make_float2(t1.x + t3.y, t1.y - t3.x);   // t1 - i*t3
    y[3] = make_float2(t1.x - t3.y, t1.y + t3.x);   // t1 + i*t3
}

// DFT8 (forward), natural-order in/out
__device__ __forceinline__ void fft8(float2 v[8]) {
    const float c = 0.70710678118654752f;
    float2 e[4], o[4];
    dft4(v[0], v[2], v[4], v[6], e);
    dft4(v[1], v[3], v[5], v[7], o);
    float2 o0 = o[0];
    float2 o1 = make_float2(c * (o[1].x + o[1].y), c * (o[1].y - o[1].x)); // *(c,-c)
    float2 o2 = make_float2(o[2].y, -o[2].x);                             // *(-i)
    float2 o3 = make_float2(c * (o[3].y - o[3].x), -c * (o[3].x + o[3].y)); // *(-c,-c)
    v[0] = caddf(e[0], o0);  v[4] = csubf(e[0], o0);
    v[1] = caddf(e[1], o1);  v[5] = csubf(e[1], o1);
    v[2] = caddf(e[2], o2);  v[6] = csubf(e[2], o2);
    v[3] = caddf(e[3], o3);  v[7] = csubf(e[3], o3);
}

// ---- shared stage-1 of DFT16 (4 dft4s + constant twiddles) -----------------
__device__ __forceinline__ void fft16_stage1(const float2 v[16],
                                             float2 y0[4], float2 y1[4],
                                             float2 y2[4], float2 y3[4]) {
    const float c1 = 0.92387953251128675f;   // cos(pi/8)
    const float s1 = 0.38268343236508977f;   // sin(pi/8)
    const float c2 = 0.70710678118654752f;
    dft4(v[0], v[4], v[8],  v[12], y0);
    dft4(v[1], v[5], v[9],  v[13], y1);
    dft4(v[2], v[6], v[10], v[14], y2);
    dft4(v[3], v[7], v[11], v[15], y3);
    y1[1] = cmulf(y1[1], make_float2( c1, -s1));
    y1[2] = cmulf(y1[2], make_float2( c2, -c2));
    y1[3] = cmulf(y1[3], make_float2( s1, -c1));
    y2[1] = cmulf(y2[1], make_float2( c2, -c2));
    y2[2] = make_float2(y2[2].y, -y2[2].x);                 // * (-i)
    y2[3] = cmulf(y2[3], make_float2(-c2, -c2));
    y3[1] = cmulf(y3[1], make_float2( s1, -c1));
    y3[2] = cmulf(y3[2], make_float2(-c2, -c2));
    y3[3] = cmulf(y3[3], make_float2(-c1,  s1));            // W16^9
}

// DFT16 (forward), natural-order in/out; full 16 outputs (inverse path).
__device__ __forceinline__ void fft16(float2 v[16]) {
    float2 y0[4], y1[4], y2[4], y3[4];
    fft16_stage1(v, y0, y1, y2, y3);
    float2 z[4];
    dft4(y0[0], y1[0], y2[0], y3[0], z); v[0]=z[0]; v[4]=z[1]; v[8] =z[2]; v[12]=z[3];
    dft4(y0[1], y1[1], y2[1], y3[1], z); v[1]=z[0]; v[5]=z[1]; v[9] =z[2]; v[13]=z[3];
    dft4(y0[2], y1[2], y2[2], y3[2], z); v[2]=z[0]; v[6]=z[1]; v[10]=z[2]; v[14]=z[3];
    dft4(y0[3], y1[3], y2[3], y3[3], z); v[3]=z[0]; v[7]=z[1]; v[11]=z[2]; v[15]=z[3];
}

// DFT16 pruned for the forward path: only outputs r in {0..3, 12..15}.
// Final dft4 bank emits z0 = t0+t2 and z3 = t1+i*t3 only (6 adds vs 8).
__device__ __forceinline__ void fft16_fwd(float2 v[16]) {
    float2 y0[4], y1[4], y2[4], y3[4];
    fft16_stage1(v, y0, y1, y2, y3);
#pragma unroll
    for (int k = 0; k < 4; k++) {
        float2 t0 = caddf(y0[k], y2[k]), t1 = csubf(y0[k], y2[k]);
        float2 t2 = caddf(y1[k], y3[k]), t3 = csubf(y1[k], y3[k]);
        v[k]      = caddf(t0, t2);
        v[k + 12] = make_float2(t1.x - t3.y, t1.y + t3.x);   // t1 + i*t3
    }
}

// ---- middle radix-8 stages (s = 1, 2) of the 8192-pt Stockham FFT ----------
// Scalar butterflies; twiddles hoisted out of the h loop:
// (tid+512) & (Ns-1) == tid & (Ns-1) for Ns in {8, 64}.
__device__ void fft_stages12(float2* S) {
    const int tid = threadIdx.x;
#pragma unroll
    for (int s = 1; s < 3; s++) {
        const int Ns    = 1 << (3 * s);
        const int shift = 10 - 3 * s;
        const int t = tid & (Ns - 1);
        const float2 w1 = twid((float)(t << shift) * ASTEP);
        const float2 w2 = cmulf(w1, w1);
        const float2 w3 = cmulf(w2, w1);
        const float2 w4 = cmulf(w2, w2);
        const float2 w5 = cmulf(w4, w1);
        const float2 w6 = cmulf(w4, w2);
        const float2 w7 = cmulf(w4, w3);
        float2 v[2][8];
        int base[2];
#pragma unroll
        for (int h = 0; h < 2; h++) {
            const int j = tid + (h << 9);
#pragma unroll
            for (int r = 0; r < 8; r++) v[h][r] = S[IDX(j + (r << 10))];
            v[h][1] = cmulf(v[h][1], w1);
            v[h][2] = cmulf(v[h][2], w2);
            v[h][3] = cmulf(v[h][3], w3);
            v[h][4] = cmulf(v[h][4], w4);
            v[h][5] = cmulf(v[h][5], w5);
            v[h][6] = cmulf(v[h][6], w6);
            v[h][7] = cmulf(v[h][7], w7);
            fft8(v[h]);
            base[h] = ((j >> (3 * s)) << (3 * s + 3)) + t;  // (j/Ns)*8Ns + t
        }
        __syncthreads();
#pragma unroll
        for (int h = 0; h < 2; h++)
#pragma unroll
            for (int r = 0; r < 8; r++)
                S[IDX(base[h] + (r << (3 * s)))] = v[h][r];
        __syncthreads();
    }
}

// ---- final radix-16 load + twiddle (shared by fwd/inv) ---------------------
__device__ __forceinline__ void radix16_load(const float2* S, int j, float2 v[16]) {
#pragma unroll
    for (int r = 0; r < 16; r++) v[r] = S[IDX(j + (r << 9))];
    const float2 w1 = twid((float)j * ASTEP);
    const float2 w2 = cmulf(w1, w1);
    const float2 w3 = cmulf(w2, w1);
    const float2 w4 = cmulf(w2, w2);
    const float2 w5 = cmulf(w4, w1);
    const float2 w6 = cmulf(w4, w2);
    const float2 w7 = cmulf(w4, w3);
    const float2 w8 = cmulf(w4, w4);
    v[1]  = cmulf(v[1],  w1);
    v[2]  = cmulf(v[2],  w2);
    v[3]  = cmulf(v[3],  w3);
    v[4]  = cmulf(v[4],  w4);
    v[5]  = cmulf(v[5],  w5);
    v[6]  = cmulf(v[6],  w6);
    v[7]  = cmulf(v[7],  w7);
    v[8]  = cmulf(v[8],  w8);
    v[9]  = cmulf(v[9],  cmulf(w8, w1));
    v[10] = cmulf(v[10], cmulf(w8, w2));
    v[11] = cmulf(v[11], cmulf(w8, w3));
    v[12] = cmulf(v[12], cmulf(w8, w4));
    v[13] = cmulf(v[13], cmulf(w8, w5));
    v[14] = cmulf(v[14], cmulf(w8, w6));
    v[15] = cmulf(v[15], cmulf(w8, w7));
}

// ---------------- kernel: forward rFFT + temb bias (fused) + modes ----------
// Per-CTA bias dot product overlapped with stage-0 gmem loads. Stage 0 reads
// directly from gmem (.cs: read-once). Tail: modes m=tid+512r (r<4) come from
// radix-16 registers (pruned fft16); mirror halves (r>=12) go to a DISJOINT
// smem buffer M -> no write-after-read hazard on S -> one barrier fewer.
__global__ void __launch_bounds__(512, 2)
k_fwd(const float* __restrict__ x, const float* __restrict__ temb,
      const float* __restrict__ dw, const float* __restrict__ db) {
    extern __shared__ float2 sm[];
    float2* S = sm;
    float2* M = sm + SBUF;                         // 2048 mirror entries
    __shared__ float s_part[16];
    __shared__ float s_bias;
    const int row = blockIdx.x;                    // b*64 + c_in
    const int bb  = row >> 6;
    const int cc  = row & 63;
    const float2* xr = (const float2*)x + (size_t)row * NF;
    const int tid = threadIdx.x;

    // ---- bias partial: one product per thread (TEMB == 512 == blockDim) ----
    {
        float tv = __ldg(&temb[bb * TEMB + tid]);
        float act = tv / (1.0f + expf(-tv));       // SiLU
        float prod = act * __ldg(&dw[(size_t)cc * TEMB + tid]);
#pragma unroll
        for (int o = 16; o; o >>= 1) prod += __shfl_xor_sync(0xffffffffu, prod, o);
        if ((tid & 31) == 0) s_part[tid >> 5] = prod;
    }

    // stage 0: Ns=1, twiddle-free, inputs straight from gmem (streaming)
    {
        float2 v[2][8];
#pragma unroll
        for (int h = 0; h < 2; h++) {
            const int j = tid + (h << 9);
#pragma unroll
            for (int r = 0; r < 8; r++) v[h][r] = __ldcs(&xr[j + (r << 10)]);
            fft8(v[h]);
        }
#pragma unroll
        for (int h = 0; h < 2; h++) {
            const int base = (tid + (h << 9)) << 3;
#pragma unroll
            for (int r = 0; r < 8; r++) S[IDX(base + r)] = v[h][r];
        }
        __syncthreads();                           // also publishes s_part
    }
    if (tid == 0) {                                // finish bias reduction
        float sum = __ldg(&db[cc]);
#pragma unroll
        for (int w = 0; w < 16; w++) sum += s_part[w];
        s_bias = sum;                              // read after later barriers
    }
    fft_stages12(S);
    float2 v[16];
    radix16_load(S, tid, v);
    fft16_fwd(v);                                  // only r in {0..3, 12..15}
    // mirror groups r in [12,16) -> disjoint buffer M (entry (tid + 512(r-12)))
#pragma unroll
    for (int r = 12; r < 16; r++) M[tid + ((r - 12) << 9)] = v[r];
    __syncthreads();
    const float tb = s_bias;
    float2* xrow = g_Xm + (size_t)row * MODES;
    // e^{-2pi i m/16384} = e0 * e^{-i pi r/16},  e0 = e^{-2pi i tid/16384}
    const float2 e0 = twid((float)tid * BSTEP);
    const float2 ER[4] = {
        make_float2(1.0f, 0.0f),
        make_float2(0.98078528040323044f, -0.19509032201612827f),
        make_float2(0.92387953251128675f, -0.38268343236508977f),
        make_float2(0.83146961230254524f, -0.55557023301960222f)
    };
#pragma unroll
    for (int r = 0; r < 4; r++) {
        const int m = tid + (r << 9);
        float2 Zm = v[r];
        float2 Zn;
        if (tid == 0) {
            Zn = (r == 0) ? v[0] : v[16 - r];       // Z[8192-512r] is own reg
        } else {
            // 8192-m = (512-tid) + 512*(15-r): stored by thread 512-tid with
            // r' = 15-r  ->  M[(512-tid) + (3-r)*512]
            Zn = M[(512 - tid) + ((3 - r) << 9)];
        }
        float2 A  = make_float2(Zm.x + Zn.x, Zm.y - Zn.y);   // Z + conj(Zn)
        float2 Bc = make_float2(Zm.x - Zn.x, Zm.y + Zn.y);   // Z - conj(Zn)
        float2 C  = cmulf(cmulf(e0, ER[r]), Bc);
        // X = 0.5*A - 0.5*i*C ; add temb bias to real part
        xrow[m] = make_float2(0.5f * (A.x + C.y) + tb, 0.5f * (A.y - C.x));
    }
}

// ---------------- kernel: mode contraction (bim,iom->bom) -------------------
// grid: 256 blocks (8 modes each); block: 256 threads =
//   [bit7]=batch-half x [bits2:7]=32 o-pairs x [bits0:2]=4 mode-pairs.
// Round-8 layout + prefetch.global.L2 at distance 4 (verified winner).
__global__ void __launch_bounds__(256, 2)
k_einsum(const float* __restrict__ wr, const float* __restrict__ wi) {
    extern __shared__ float4 Xc[];                 // [ (b*64+i)*4 + mg ] 64KB
    const int m0  = blockIdx.x * 8;
    const int tid = threadIdx.x;
    for (int idx = tid; idx < BB * CIN * 4; idx += 256) {
        const int p  = idx & 3;
        const int bi = idx >> 2;
        float4 q = *((const float4*)(g_Xm + (size_t)bi * MODES + m0) + p);
        Xc[idx] = make_float4(q.x, q.z, q.y, q.w); // (re0, re1, im0, im1)
    }
    __syncthreads();
    const int mg = tid & 3;
    const int op = (tid >> 2) & 31;
    const int bh = tid >> 7;
    const int o0 = 2 * op;
    const int m  = m0 + 2 * mg;
    const int b0 = bh * 8;

    unsigned long long ar[2][8], ai[2][8];
#pragma unroll
    for (int k = 0; k < 2; k++)
#pragma unroll
        for (int b = 0; b < 8; b++) { ar[k][b] = 0ULL; ai[k][b] = 0ULL; }

    const size_t istep = (size_t)COUT * MODES;
    size_t off = (size_t)o0 * MODES + m;
    unsigned long long cwr0 = *(const unsigned long long*)(wr + off);
    unsigned long long cwr1 = *(const unsigned long long*)(wr + off + MODES);
    unsigned long long cwi0 = *(const unsigned long long*)(wi + off);
    unsigned long long cwi1 = *(const unsigned long long*)(wi + off + MODES);

    for (int i = 0; i < CIN; i++) {
        unsigned long long nwr0, nwr1, nwi0, nwi1;
        if (i + 1 < CIN) {                          // register prefetch, d=1
            const size_t noff = off + istep;
            nwr0 = *(const unsigned long long*)(wr + noff);
            nwr1 = *(const unsigned long long*)(wr + noff + MODES);
            nwi0 = *(const unsigned long long*)(wi + noff);
            nwi1 = *(const unsigned long long*)(wi + noff + MODES);
        }
        if (i + 4 < CIN) {                          // L2 prefetch, distance 4
            const size_t poff = off + 4 * istep;
            asm volatile("prefetch.global.L2 [%0];" :: "l"(wr + poff));
            asm volatile("prefetch.global.L2 [%0];" :: "l"(wr + poff + MODES));
            asm volatile("prefetch.global.L2 [%0];" :: "l"(wi + poff));
            asm volatile("prefetch.global.L2 [%0];" :: "l"(wi + poff + MODES));
        }
#pragma unroll
        for (int b = 0; b < 8; b++) {
            const int idx2 = ((b0 + b) * CIN + i) * 4 + mg;
            const ulonglong2 xu = *(const ulonglong2*)(Xc + idx2); // 1 LDS.128
            const unsigned long long xr2  = xu.x;                  // (re0,re1)
            const unsigned long long xi2  = xu.y;                  // (im0,im1)
            const unsigned long long xin2 = xi2 ^ 0x8000000080000000ULL;
            ar[0][b] = fma2(xr2,  cwr0, ar[0][b]);
            ar[0][b] = fma2(xin2, cwi0, ar[0][b]);
            ai[0][b] = fma2(xr2,  cwi0, ai[0][b]);
            ai[0][b] = fma2(xi2,  cwr0, ai[0][b]);
            ar[1][b] = fma2(xr2,  cwr1, ar[1][b]);
            ar[1][b] = fma2(xin2, cwi1, ar[1][b]);
            ai[1][b] = fma2(xr2,  cwi1, ai[1][b]);
            ai[1][b] = fma2(xi2,  cwr1, ai[1][b]);
        }
        cwr0 = nwr0; cwr1 = nwr1; cwi0 = nwi0; cwi1 = nwi1;
        off += istep;
    }
#pragma unroll
    for (int k = 0; k < 2; k++)
#pragma unroll
        for (int b = 0; b < 8; b++) {
            float r0, r1, i0, i1;
            asm("mov.b64 {%0, %1}, %2;" : "=f"(r0), "=f"(r1) : "l"(ar[k][b]));
            asm("mov.b64 {%0, %1}, %2;" : "=f"(i0), "=f"(i1) : "l"(ai[k][b]));
            const size_t ob = ((size_t)((b0 + b) * COUT + o0 + k)) * MODES + m;
            *((float4*)(g_Om + ob)) = make_float4(r0, i0, r1, i1);
        }
}

// ---------------- kernel: inverse rFFT --------------------------------------
// Stage 0 builds the Hermitian-packed spectrum in REGISTERS from g_Om
// (only r in {0,1,6,7} nonzero); final radix-16 writes straight to gmem (.cs).
// Stage-0 twiddles: ONE sincos per half, then constant rotations e^{-i pi r/8}.
__global__ void __launch_bounds__(512, 2)
k_inv(float* __restrict__ out) {
    extern __shared__ float2 sm[];
    float2* S = sm;
    const int row = blockIdx.x;                    // b*64 + c_out
    const float2* orow = g_Om + (size_t)row * MODES;
    const int tid = threadIdx.x;
    // stage 0 (Ns=1, twiddle-free): inputs computed inline
    {
        float2 v[2][8];
#pragma unroll
        for (int h = 0; h < 2; h++) {
            const int j = tid + (h << 9);
            const float2 e0 = twid((float)j * BSTEP);  // e^{-2pi i j/16384}
#pragma unroll
            for (int r = 0; r < 8; r++) {
                if (r >= 2 && r <= 5) { v[h][r] = make_float2(0.0f, 0.0f); continue; }
                const int mm = j + (r << 10);
                float2 Xm = make_float2(0.0f, 0.0f);
                float2 Cc = make_float2(0.0f, 0.0f);
                if (r < 2) {                       // mm < 2048
                    Xm = __ldg(&orow[mm]);
                    if (mm == 0) Xm.y = 0.0f;      // irfft drops Im(X[0])
                } else {                           // r>=6: mirror branch
                    const int mr = NF - mm;
                    if (mr < MODES) {
                        float2 q = __ldg(&orow[mr]);
                        Cc = make_float2(q.x, -q.y);
                    }
                }
                float2 Ze = make_float2(0.5f * (Xm.x + Cc.x), 0.5f * (Xm.y + Cc.y));
                float2 D  = make_float2(0.5f * (Xm.x - Cc.x), 0.5f * (Xm.y - Cc.y));
                // e = e0 * e^{-i pi r/8} (constants for r in {0,1,6,7})
                float2 er;
                if (r == 0)      er = e0;
                else if (r == 1) er = cmulf(e0, make_float2( 0.92387953251128675f, -0.38268343236508977f));
                else if (r == 6) er = cmulf(e0, make_float2(-0.70710678118654752f, -0.70710678118654752f));
                else             er = cmulf(e0, make_float2(-0.92387953251128675f, -0.38268343236508977f));
                float2 Zo = cmulf(make_float2(er.x, -er.y), D);
                // Z = Ze + i*Zo ; store conj(Z) so forward FFT computes inverse
                v[h][r] = make_float2(Ze.x - Zo.y, -(Ze.y + Zo.x));
            }
            fft8(v[h]);
        }
#pragma unroll
        for (int h = 0; h < 2; h++) {
            const int base = (tid + (h << 9)) << 3;
#pragma unroll
            for (int r = 0; r < 8; r++) S[IDX(base + r)] = v[h][r];
        }
        __syncthreads();
    }
    fft_stages12(S);
    // final radix-16: write results straight to gmem (index j + 512r)
    {
        float2 v[16];
        radix16_load(S, tid, v);
        fft16(v);
        const float sc = 1.0f / 8192.0f;
        float2* outr = (float2*)out + (size_t)row * NF;
#pragma unroll
        for (int r = 0; r < 16; r++) {
            float2 z = v[r];
            __stcs(&outr[tid + (r << 9)],
                   make_float2(z.x * sc, -z.y * sc));   // conj + 1/N, streaming
        }
    }
}

// ---------------- launch ----------------------------------------------------
extern "C" void kernel_launch(void* const* d_in, const int* in_sizes, int n_in,
                              void* d_out, int out_size) {
    const float* x    = (const float*)d_in[0];
    const float* temb = (const float*)d_in[1];
    const float* wr   = (const float*)d_in[2];
    const float* wi   = (const float*)d_in[3];
    const float* dw   = (const float*)d_in[4];
    const float* db   = (const float*)d_in[5];
    float* out = (float*)d_out;

    cudaFuncSetAttribute(k_fwd,    cudaFuncAttributeMaxDynamicSharedMemorySize, FWD_SMEM);
    cudaFuncSetAttribute(k_inv,    cudaFuncAttributeMaxDynamicSharedMemorySize, SBUF * 8);
    cudaFuncSetAttribute(k_einsum, cudaFuncAttributeMaxDynamicSharedMemorySize, 65536);

    k_fwd   <<<BB * CIN, 512, FWD_SMEM>>>(x, temb, dw, db);
    k_einsum<<<MODES / 8, 256, 65536>>>(wr, wi);
    k_inv   <<<BB * COUT, 512, SBUF * 8>>>(out);
}